// round 8
// baseline (speedup 1.0000x reference)
#include <cuda_runtime.h>

#define D   48
#define NN  100000
#define NE  1600000
#define NL  6
#define NG  1000

__device__ __align__(16) float g_h[NN * D];
__device__ __align__(16) float g_agg[NN * D];

typedef unsigned long long u64;

__device__ __forceinline__ u64 pack2(float v) {
    u64 r; asm("mov.b64 %0, {%1, %1};" : "=l"(r) : "f"(v)); return r;
}
__device__ __forceinline__ void unpack2(u64 v, float& lo, float& hi) {
    asm("mov.b64 {%0, %1}, %2;" : "=f"(lo), "=f"(hi) : "l"(v));
}
__device__ __forceinline__ u64 ffma2(u64 a, u64 b, u64 c) {
    u64 d; asm("fma.rn.f32x2 %0, %1, %2, %3;" : "=l"(d) : "l"(a), "l"(b), "l"(c));
    return d;
}

// ---------------------------------------------------------------------------
// Two-layer MLP, k-tiled to shrink the register live set:
//   for each tile t (12 hidden units):
//     acc1[6] = b1 tile; accumulate over all 48 inputs (x from smem column)
//     relu -> r[12]; immediately fold into acc2[24] (layer-2 partial)
// Accumulation order over i is ascending in both layers => numerically
// identical to the straight version.
// sx = per-thread smem column base (stride 128 floats), conflict-free,
// no syncs needed (each thread touches only its own column).
// ---------------------------------------------------------------------------
__device__ __forceinline__ void mlp2_tiled(const float* __restrict__ sx,
                                           const float* __restrict__ s_w1,
                                           const float* __restrict__ s_b1,
                                           const float* __restrict__ s_w2,
                                           const float* __restrict__ s_b2,
                                           float* __restrict__ m) {
    u64 acc2[24];
    {
        const u64* bp = (const u64*)s_b2;
#pragma unroll
        for (int k = 0; k < 24; k++) acc2[k] = bp[k];
    }

#pragma unroll
    for (int t = 0; t < 4; t++) {
        // ---- layer 1, 12 outputs ----
        u64 acc1[6];
        {
            const u64* bp = (const u64*)(s_b1 + t * 12);
#pragma unroll
            for (int k = 0; k < 6; k++) acc1[k] = bp[k];
        }
#pragma unroll 12
        for (int i = 0; i < D; i++) {
            u64 xx = pack2(sx[i * 128]);
            const ulonglong2* w = (const ulonglong2*)(s_w1 + i * D + t * 12);
            ulonglong2 wa = w[0];
            ulonglong2 wb = w[1];
            ulonglong2 wc = w[2];
            acc1[0] = ffma2(xx, wa.x, acc1[0]);
            acc1[1] = ffma2(xx, wa.y, acc1[1]);
            acc1[2] = ffma2(xx, wb.x, acc1[2]);
            acc1[3] = ffma2(xx, wb.y, acc1[3]);
            acc1[4] = ffma2(xx, wc.x, acc1[4]);
            acc1[5] = ffma2(xx, wc.y, acc1[5]);
        }
        // ---- relu -> r[12], fold into layer 2 ----
        float r[12];
#pragma unroll
        for (int k = 0; k < 6; k++) {
            float lo, hi; unpack2(acc1[k], lo, hi);
            r[2 * k]     = fmaxf(lo, 0.f);
            r[2 * k + 1] = fmaxf(hi, 0.f);
        }
#pragma unroll 6
        for (int j = 0; j < 12; j++) {
            u64 rr = pack2(r[j]);
            const ulonglong2* w = (const ulonglong2*)(s_w2 + (t * 12 + j) * D);
#pragma unroll
            for (int k = 0; k < 12; k++) {
                ulonglong2 ww = w[k];
                acc2[2 * k]     = ffma2(rr, ww.x, acc2[2 * k]);
                acc2[2 * k + 1] = ffma2(rr, ww.y, acc2[2 * k + 1]);
            }
        }
    }

#pragma unroll
    for (int k = 0; k < 24; k++) unpack2(acc2[k], m[2 * k], m[2 * k + 1]);
}

// register-x single hidden layer (small readout kernel only)
__device__ __forceinline__ void mlp_hidden_reg(const float* x, const float* s_w1,
                                               const float* s_b1, float* r) {
    u64 acc[24];
    const u64* bp = (const u64*)s_b1;
#pragma unroll
    for (int k = 0; k < 24; k++) acc[k] = bp[k];
#pragma unroll 8
    for (int i = 0; i < D; i++) {
        u64 xx = pack2(x[i]);
        const ulonglong2* w = (const ulonglong2*)(s_w1 + i * D);
#pragma unroll
        for (int k = 0; k < 12; k++) {
            ulonglong2 ww = w[k];
            acc[2 * k]     = ffma2(xx, ww.x, acc[2 * k]);
            acc[2 * k + 1] = ffma2(xx, ww.y, acc[2 * k + 1]);
        }
    }
#pragma unroll
    for (int k = 0; k < 24; k++) {
        float lo, hi; unpack2(acc[k], lo, hi);
        r[2 * k]     = fmaxf(lo, 0.f);
        r[2 * k + 1] = fmaxf(hi, 0.f);
    }
}

__global__ void __launch_bounds__(128) embed_kernel(const int* __restrict__ an,
                                                    const float* __restrict__ emb) {
    int n = blockIdx.x * 128 + threadIdx.x;
    if (n >= NN) return;
    const float4* e = (const float4*)(emb + (size_t)an[n] * D);
    float4* hp = (float4*)(g_h + (size_t)n * D);
#pragma unroll
    for (int q = 0; q < 12; q++) hp[q] = e[q];
}

__global__ void __launch_bounds__(256) zero_agg_kernel() {
    int t = blockIdx.x * 256 + threadIdx.x;
    if (t < NN * D / 4) ((float4*)g_agg)[t] = make_float4(0.f, 0.f, 0.f, 0.f);
}

__global__ void __launch_bounds__(256) zero_out_kernel(float* out) {
    int t = blockIdx.x * 256 + threadIdx.x;
    if (t < NG) out[t] = 0.f;
}

// NE % 128 == 0 -> no bounds guard needed
__global__ void __launch_bounds__(128) edge_kernel(const int* __restrict__ edge,
                                                   const float* __restrict__ w1,
                                                   const float* __restrict__ b1,
                                                   const float* __restrict__ w2,
                                                   const float* __restrict__ b2) {
    __shared__ __align__(16) float s_w1[D * D];
    __shared__ __align__(16) float s_w2[D * D];
    __shared__ __align__(16) float s_b1[D];
    __shared__ __align__(16) float s_b2[D];
    __shared__ __align__(16) float s_x[D * 128];   // 24 KB, 1 column/thread

    int tid = threadIdx.x;
    for (int t = tid; t < D * D; t += 128) { s_w1[t] = w1[t]; s_w2[t] = w2[t]; }
    if (tid < D) { s_b1[tid] = b1[tid]; s_b2[tid] = b2[tid]; }
    __syncthreads();

    int e = blockIdx.x * 128 + tid;
    int src = edge[e];
    int dst = edge[NE + e];

    float* sx = s_x + tid;
    const float4* hs = (const float4*)(g_h + (size_t)src * D);
    const float4* hd = (const float4*)(g_h + (size_t)dst * D);
#pragma unroll
    for (int q = 0; q < 12; q++) {
        float4 a = hs[q], b = hd[q];
        sx[(4 * q + 0) * 128] = a.x * b.x;
        sx[(4 * q + 1) * 128] = a.y * b.y;
        sx[(4 * q + 2) * 128] = a.z * b.z;
        sx[(4 * q + 3) * 128] = a.w * b.w;
    }

    float m[D];
    mlp2_tiled(sx, s_w1, s_b1, s_w2, s_b2, m);

    float* aggp = g_agg + (size_t)dst * D;
#pragma unroll
    for (int q = 0; q < 12; q++) {
        asm volatile("red.global.add.v4.f32 [%0], {%1, %2, %3, %4};"
                     :: "l"(aggp + 4 * q),
                        "f"(m[4 * q + 0]), "f"(m[4 * q + 1]),
                        "f"(m[4 * q + 2]), "f"(m[4 * q + 3])
                     : "memory");
    }
}

__global__ void __launch_bounds__(128) update_kernel(const float* __restrict__ w1,
                                                     const float* __restrict__ b1,
                                                     const float* __restrict__ w2,
                                                     const float* __restrict__ b2) {
    __shared__ __align__(16) float s_w1[D * D];
    __shared__ __align__(16) float s_w2[D * D];
    __shared__ __align__(16) float s_b1[D];
    __shared__ __align__(16) float s_b2[D];
    __shared__ __align__(16) float s_x[D * 128];

    int tid = threadIdx.x;
    for (int t = tid; t < D * D; t += 128) { s_w1[t] = w1[t]; s_w2[t] = w2[t]; }
    if (tid < D) { s_b1[tid] = b1[tid]; s_b2[tid] = b2[tid]; }
    __syncthreads();

    int n = blockIdx.x * 128 + tid;
    bool valid = (n < NN);

    float* sx = s_x + tid;
    if (valid) {
        const float4* ap = (const float4*)(g_agg + (size_t)n * D);
#pragma unroll
        for (int q = 0; q < 12; q++) {
            float4 a = ap[q];
            sx[(4 * q + 0) * 128] = a.x;
            sx[(4 * q + 1) * 128] = a.y;
            sx[(4 * q + 2) * 128] = a.z;
            sx[(4 * q + 3) * 128] = a.w;
        }
    } else {
#pragma unroll
        for (int q = 0; q < D; q++) sx[q * 128] = 0.f;
    }

    float u[D];
    mlp2_tiled(sx, s_w1, s_b1, s_w2, s_b2, u);

    if (valid) {
        float4* hp = (float4*)(g_h + (size_t)n * D);
#pragma unroll
        for (int q = 0; q < 12; q++) {
            float4 hv = hp[q];
            hv.x += u[4 * q + 0]; hv.y += u[4 * q + 1];
            hv.z += u[4 * q + 2]; hv.w += u[4 * q + 3];
            hp[q] = hv;
        }
    }
}

__global__ void __launch_bounds__(128) readout_kernel(const float* __restrict__ w1,
                                                      const float* __restrict__ b1,
                                                      const float* __restrict__ w2v,
                                                      const float* __restrict__ b2s,
                                                      const int* __restrict__ gid,
                                                      float* __restrict__ out) {
    __shared__ __align__(16) float s_w1[D * D];
    __shared__ __align__(16) float s_b1[D];
    __shared__ __align__(16) float s_w2[D];
    __shared__ float s_b2;
    for (int t = threadIdx.x; t < D * D; t += 128) s_w1[t] = w1[t];
    if (threadIdx.x < D) { s_b1[threadIdx.x] = b1[threadIdx.x]; s_w2[threadIdx.x] = w2v[threadIdx.x]; }
    if (threadIdx.x == 0) s_b2 = b2s[0];
    __syncthreads();

    int n = blockIdx.x * 128 + threadIdx.x;
    if (n >= NN) return;

    const float4* hp = (const float4*)(g_h + (size_t)n * D);
    float x[D];
#pragma unroll
    for (int q = 0; q < 12; q++) {
        float4 a = hp[q];
        x[4 * q + 0] = a.x; x[4 * q + 1] = a.y; x[4 * q + 2] = a.z; x[4 * q + 3] = a.w;
    }

    float r[D];
    mlp_hidden_reg(x, s_w1, s_b1, r);

    float y = s_b2;
#pragma unroll
    for (int k = 0; k < D; k++) y += r[k] * s_w2[k];

    atomicAdd(&out[gid[n]], y);
}

extern "C" void kernel_launch(void* const* d_in, const int* in_sizes, int n_in,
                              void* d_out, int out_size) {
    const int*   AtomicNum = (const int*)d_in[0];
    const int*   Edge      = (const int*)d_in[1];
    const int*   graph_id  = (const int*)d_in[2];
    const float* emb       = (const float*)d_in[3];
    const float* msg_w1    = (const float*)d_in[4];
    const float* msg_b1    = (const float*)d_in[5];
    const float* msg_w2    = (const float*)d_in[6];
    const float* msg_b2    = (const float*)d_in[7];
    const float* upd_w1    = (const float*)d_in[8];
    const float* upd_b1    = (const float*)d_in[9];
    const float* upd_w2    = (const float*)d_in[10];
    const float* upd_b2    = (const float*)d_in[11];
    const float* ro_w1     = (const float*)d_in[12];
    const float* ro_b1     = (const float*)d_in[13];
    const float* ro_w2     = (const float*)d_in[14];
    const float* ro_b2     = (const float*)d_in[15];
    float* out = (float*)d_out;

    embed_kernel<<<(NN + 127) / 128, 128>>>(AtomicNum, emb);

    const int zero_blocks = (NN * D / 4 + 255) / 256;
    const int edge_blocks = NE / 128;           // exact
    const int node_blocks = (NN + 127) / 128;

    for (int l = 0; l < NL; l++) {
        zero_agg_kernel<<<zero_blocks, 256>>>();
        edge_kernel<<<edge_blocks, 128>>>(Edge,
                                          msg_w1 + (size_t)l * D * D, msg_b1 + (size_t)l * D,
                                          msg_w2 + (size_t)l * D * D, msg_b2 + (size_t)l * D);
        update_kernel<<<node_blocks, 128>>>(upd_w1 + (size_t)l * D * D, upd_b1 + (size_t)l * D,
                                            upd_w2 + (size_t)l * D * D, upd_b2 + (size_t)l * D);
    }

    zero_out_kernel<<<(NG + 255) / 256, 256>>>(out);
    readout_kernel<<<node_blocks, 128>>>(ro_w1, ro_b1, ro_w2, ro_b2, graph_id, out);
}

// round 9
// speedup vs baseline: 1.3515x; 1.3515x over previous
#include <cuda_runtime.h>

#define D   48
#define NN  100000
#define NE  1600000
#define NL  6
#define NG  1000

__device__ __align__(16) float g_h[NN * D];
__device__ __align__(16) float g_agg[NN * D];

typedef unsigned long long u64;

__device__ __forceinline__ u64 pack2(float v) {
    u64 r; asm("mov.b64 %0, {%1, %1};" : "=l"(r) : "f"(v)); return r;
}
__device__ __forceinline__ void unpack2(u64 v, float& lo, float& hi) {
    asm("mov.b64 {%0, %1}, %2;" : "=f"(lo), "=f"(hi) : "l"(v));
}
__device__ __forceinline__ u64 ffma2(u64 a, u64 b, u64 c) {
    u64 d; asm("fma.rn.f32x2 %0, %1, %2, %3;" : "=l"(d) : "l"(a), "l"(b), "l"(c));
    return d;
}

// ---------------------------------------------------------------------------
// Block-GEMM two-layer MLP over 128 items (one column per item in s_x,
// layout s_x[i*128 + item], i = feature index 0..47).
// Thread (a = tid&31, b = tid>>5) computes items {a, a+32, a+64, a+96} for
// output slice [b*12, (b+1)*12). Weight-segment loads are warp-uniform
// (all lanes of a warp share b -> LDS broadcast); x loads are consecutive
// across lanes -> conflict-free.
// Caller must have filled s_x and issued __syncthreads() before calling.
// On return, m[e*12 + j] = output j of slice for item a+32e.
// Accumulation over i is ascending in both layers (matches reference order).
// ---------------------------------------------------------------------------
__device__ __forceinline__ void mlp2_gemm(float* __restrict__ s_x,
                                          const float* __restrict__ s_w1,
                                          const float* __restrict__ s_b1,
                                          const float* __restrict__ s_w2,
                                          const float* __restrict__ s_b2,
                                          int a, int b,
                                          float* __restrict__ m) {
    u64 acc[4][6];
    // ---- layer 1 ----
    {
        const u64* bp = (const u64*)(s_b1 + b * 12);
        u64 b0 = bp[0], b1 = bp[1], b2 = bp[2], b3 = bp[3], b4 = bp[4], b5 = bp[5];
#pragma unroll
        for (int e = 0; e < 4; e++) {
            acc[e][0] = b0; acc[e][1] = b1; acc[e][2] = b2;
            acc[e][3] = b3; acc[e][4] = b4; acc[e][5] = b5;
        }
    }
#pragma unroll 4
    for (int i = 0; i < D; i++) {
        const ulonglong2* w = (const ulonglong2*)(s_w1 + i * D + b * 12);
        ulonglong2 wa = w[0], wb = w[1], wc = w[2];
        const float* xr = s_x + i * 128 + a;
        float x0 = xr[0], x1 = xr[32], x2 = xr[64], x3 = xr[96];
        u64 xx;
        xx = pack2(x0);
        acc[0][0] = ffma2(xx, wa.x, acc[0][0]); acc[0][1] = ffma2(xx, wa.y, acc[0][1]);
        acc[0][2] = ffma2(xx, wb.x, acc[0][2]); acc[0][3] = ffma2(xx, wb.y, acc[0][3]);
        acc[0][4] = ffma2(xx, wc.x, acc[0][4]); acc[0][5] = ffma2(xx, wc.y, acc[0][5]);
        xx = pack2(x1);
        acc[1][0] = ffma2(xx, wa.x, acc[1][0]); acc[1][1] = ffma2(xx, wa.y, acc[1][1]);
        acc[1][2] = ffma2(xx, wb.x, acc[1][2]); acc[1][3] = ffma2(xx, wb.y, acc[1][3]);
        acc[1][4] = ffma2(xx, wc.x, acc[1][4]); acc[1][5] = ffma2(xx, wc.y, acc[1][5]);
        xx = pack2(x2);
        acc[2][0] = ffma2(xx, wa.x, acc[2][0]); acc[2][1] = ffma2(xx, wa.y, acc[2][1]);
        acc[2][2] = ffma2(xx, wb.x, acc[2][2]); acc[2][3] = ffma2(xx, wb.y, acc[2][3]);
        acc[2][4] = ffma2(xx, wc.x, acc[2][4]); acc[2][5] = ffma2(xx, wc.y, acc[2][5]);
        xx = pack2(x3);
        acc[3][0] = ffma2(xx, wa.x, acc[3][0]); acc[3][1] = ffma2(xx, wa.y, acc[3][1]);
        acc[3][2] = ffma2(xx, wb.x, acc[3][2]); acc[3][3] = ffma2(xx, wb.y, acc[3][3]);
        acc[3][4] = ffma2(xx, wc.x, acc[3][4]); acc[3][5] = ffma2(xx, wc.y, acc[3][5]);
    }

    // all layer-1 reads of s_x are done; overwrite with relu'd hidden acts
    __syncthreads();
#pragma unroll
    for (int e = 0; e < 4; e++) {
        float* col = s_x + 32 * e + a;
#pragma unroll
        for (int k = 0; k < 6; k++) {
            float lo, hi; unpack2(acc[e][k], lo, hi);
            col[(b * 12 + 2 * k) * 128]     = fmaxf(lo, 0.f);
            col[(b * 12 + 2 * k + 1) * 128] = fmaxf(hi, 0.f);
        }
    }
    __syncthreads();

    // ---- layer 2 ----
    {
        const u64* bp = (const u64*)(s_b2 + b * 12);
        u64 b0 = bp[0], b1 = bp[1], b2 = bp[2], b3 = bp[3], b4 = bp[4], b5 = bp[5];
#pragma unroll
        for (int e = 0; e < 4; e++) {
            acc[e][0] = b0; acc[e][1] = b1; acc[e][2] = b2;
            acc[e][3] = b3; acc[e][4] = b4; acc[e][5] = b5;
        }
    }
#pragma unroll 4
    for (int i = 0; i < D; i++) {
        const ulonglong2* w = (const ulonglong2*)(s_w2 + i * D + b * 12);
        ulonglong2 wa = w[0], wb = w[1], wc = w[2];
        const float* xr = s_x + i * 128 + a;
        float x0 = xr[0], x1 = xr[32], x2 = xr[64], x3 = xr[96];
        u64 xx;
        xx = pack2(x0);
        acc[0][0] = ffma2(xx, wa.x, acc[0][0]); acc[0][1] = ffma2(xx, wa.y, acc[0][1]);
        acc[0][2] = ffma2(xx, wb.x, acc[0][2]); acc[0][3] = ffma2(xx, wb.y, acc[0][3]);
        acc[0][4] = ffma2(xx, wc.x, acc[0][4]); acc[0][5] = ffma2(xx, wc.y, acc[0][5]);
        xx = pack2(x1);
        acc[1][0] = ffma2(xx, wa.x, acc[1][0]); acc[1][1] = ffma2(xx, wa.y, acc[1][1]);
        acc[1][2] = ffma2(xx, wb.x, acc[1][2]); acc[1][3] = ffma2(xx, wb.y, acc[1][3]);
        acc[1][4] = ffma2(xx, wc.x, acc[1][4]); acc[1][5] = ffma2(xx, wc.y, acc[1][5]);
        xx = pack2(x2);
        acc[2][0] = ffma2(xx, wa.x, acc[2][0]); acc[2][1] = ffma2(xx, wa.y, acc[2][1]);
        acc[2][2] = ffma2(xx, wb.x, acc[2][2]); acc[2][3] = ffma2(xx, wb.y, acc[2][3]);
        acc[2][4] = ffma2(xx, wc.x, acc[2][4]); acc[2][5] = ffma2(xx, wc.y, acc[2][5]);
        xx = pack2(x3);
        acc[3][0] = ffma2(xx, wa.x, acc[3][0]); acc[3][1] = ffma2(xx, wa.y, acc[3][1]);
        acc[3][2] = ffma2(xx, wb.x, acc[3][2]); acc[3][3] = ffma2(xx, wb.y, acc[3][3]);
        acc[3][4] = ffma2(xx, wc.x, acc[3][4]); acc[3][5] = ffma2(xx, wc.y, acc[3][5]);
    }

#pragma unroll
    for (int e = 0; e < 4; e++)
#pragma unroll
        for (int k = 0; k < 6; k++)
            unpack2(acc[e][k], m[e * 12 + 2 * k], m[e * 12 + 2 * k + 1]);
}

// register-x single hidden layer (small readout kernel only)
__device__ __forceinline__ void mlp_hidden_reg(const float* x, const float* s_w1,
                                               const float* s_b1, float* r) {
    u64 acc[24];
    const u64* bp = (const u64*)s_b1;
#pragma unroll
    for (int k = 0; k < 24; k++) acc[k] = bp[k];
#pragma unroll 8
    for (int i = 0; i < D; i++) {
        u64 xx = pack2(x[i]);
        const ulonglong2* w = (const ulonglong2*)(s_w1 + i * D);
#pragma unroll
        for (int k = 0; k < 12; k++) {
            ulonglong2 ww = w[k];
            acc[2 * k]     = ffma2(xx, ww.x, acc[2 * k]);
            acc[2 * k + 1] = ffma2(xx, ww.y, acc[2 * k + 1]);
        }
    }
#pragma unroll
    for (int k = 0; k < 24; k++) {
        float lo, hi; unpack2(acc[k], lo, hi);
        r[2 * k]     = fmaxf(lo, 0.f);
        r[2 * k + 1] = fmaxf(hi, 0.f);
    }
}

__global__ void __launch_bounds__(128) embed_kernel(const int* __restrict__ an,
                                                    const float* __restrict__ emb) {
    int n = blockIdx.x * 128 + threadIdx.x;
    if (n >= NN) return;
    const float4* e = (const float4*)(emb + (size_t)an[n] * D);
    float4* hp = (float4*)(g_h + (size_t)n * D);
#pragma unroll
    for (int q = 0; q < 12; q++) hp[q] = e[q];
}

__global__ void __launch_bounds__(256) zero_agg_kernel() {
    int t = blockIdx.x * 256 + threadIdx.x;
    if (t < NN * D / 4) ((float4*)g_agg)[t] = make_float4(0.f, 0.f, 0.f, 0.f);
}

__global__ void __launch_bounds__(256) zero_out_kernel(float* out) {
    int t = blockIdx.x * 256 + threadIdx.x;
    if (t < NG) out[t] = 0.f;
}

// NE % 128 == 0 -> no bounds guard needed
__global__ void __launch_bounds__(128) edge_kernel(const int* __restrict__ edge,
                                                   const float* __restrict__ w1,
                                                   const float* __restrict__ b1,
                                                   const float* __restrict__ w2,
                                                   const float* __restrict__ b2) {
    __shared__ __align__(16) float s_w1[D * D];
    __shared__ __align__(16) float s_w2[D * D];
    __shared__ __align__(16) float s_b1[D];
    __shared__ __align__(16) float s_b2[D];
    __shared__ __align__(16) float s_x[D * 128];   // 24 KB: [i][item]

    int tid = threadIdx.x;
    for (int t = tid; t < D * D; t += 128) { s_w1[t] = w1[t]; s_w2[t] = w2[t]; }
    if (tid < D) { s_b1[tid] = b1[tid]; s_b2[tid] = b2[tid]; }

    // fill phase: thread tid owns item tid
    int e0 = blockIdx.x * 128 + tid;
    int src = edge[e0];
    int dst0 = edge[NE + e0];
    {
        const float4* hs = (const float4*)(g_h + (size_t)src * D);
        const float4* hd = (const float4*)(g_h + (size_t)dst0 * D);
        float* col = s_x + tid;
#pragma unroll
        for (int q = 0; q < 12; q++) {
            float4 va = hs[q], vb = hd[q];
            col[(4 * q + 0) * 128] = va.x * vb.x;
            col[(4 * q + 1) * 128] = va.y * vb.y;
            col[(4 * q + 2) * 128] = va.z * vb.z;
            col[(4 * q + 3) * 128] = va.w * vb.w;
        }
    }
    __syncthreads();

    int a = tid & 31, b = tid >> 5;
    // dst indices of the 4 items this thread emits
    int dste[4];
#pragma unroll
    for (int e = 0; e < 4; e++) dste[e] = edge[NE + blockIdx.x * 128 + 32 * e + a];

    float m[48];
    mlp2_gemm(s_x, s_w1, s_b1, s_w2, s_b2, a, b, m);

#pragma unroll
    for (int e = 0; e < 4; e++) {
        float* aggp = g_agg + (size_t)dste[e] * D + b * 12;
#pragma unroll
        for (int q = 0; q < 3; q++) {
            asm volatile("red.global.add.v4.f32 [%0], {%1, %2, %3, %4};"
                         :: "l"(aggp + 4 * q),
                            "f"(m[e * 12 + 4 * q + 0]), "f"(m[e * 12 + 4 * q + 1]),
                            "f"(m[e * 12 + 4 * q + 2]), "f"(m[e * 12 + 4 * q + 3])
                         : "memory");
        }
    }
}

__global__ void __launch_bounds__(128) update_kernel(const float* __restrict__ w1,
                                                     const float* __restrict__ b1,
                                                     const float* __restrict__ w2,
                                                     const float* __restrict__ b2) {
    __shared__ __align__(16) float s_w1[D * D];
    __shared__ __align__(16) float s_w2[D * D];
    __shared__ __align__(16) float s_b1[D];
    __shared__ __align__(16) float s_b2[D];
    __shared__ __align__(16) float s_x[D * 128];

    int tid = threadIdx.x;
    for (int t = tid; t < D * D; t += 128) { s_w1[t] = w1[t]; s_w2[t] = w2[t]; }
    if (tid < D) { s_b1[tid] = b1[tid]; s_b2[tid] = b2[tid]; }

    int base = blockIdx.x * 128;
    {
        int n = base + tid;
        float* col = s_x + tid;
        if (n < NN) {
            const float4* ap = (const float4*)(g_agg + (size_t)n * D);
#pragma unroll
            for (int q = 0; q < 12; q++) {
                float4 v = ap[q];
                col[(4 * q + 0) * 128] = v.x;
                col[(4 * q + 1) * 128] = v.y;
                col[(4 * q + 2) * 128] = v.z;
                col[(4 * q + 3) * 128] = v.w;
            }
        } else {
#pragma unroll
            for (int q = 0; q < D; q++) col[q * 128] = 0.f;
        }
    }
    __syncthreads();

    int a = tid & 31, b = tid >> 5;
    float u[48];
    mlp2_gemm(s_x, s_w1, s_b1, s_w2, s_b2, a, b, u);

#pragma unroll
    for (int e = 0; e < 4; e++) {
        int n = base + 32 * e + a;
        if (n < NN) {
            float4* hp = (float4*)(g_h + (size_t)n * D + b * 12);
#pragma unroll
            for (int q = 0; q < 3; q++) {
                float4 hv = hp[q];
                hv.x += u[e * 12 + 4 * q + 0];
                hv.y += u[e * 12 + 4 * q + 1];
                hv.z += u[e * 12 + 4 * q + 2];
                hv.w += u[e * 12 + 4 * q + 3];
                hp[q] = hv;
            }
        }
    }
}

__global__ void __launch_bounds__(128) readout_kernel(const float* __restrict__ w1,
                                                      const float* __restrict__ b1,
                                                      const float* __restrict__ w2v,
                                                      const float* __restrict__ b2s,
                                                      const int* __restrict__ gid,
                                                      float* __restrict__ out) {
    __shared__ __align__(16) float s_w1[D * D];
    __shared__ __align__(16) float s_b1[D];
    __shared__ __align__(16) float s_w2[D];
    __shared__ float s_b2;
    for (int t = threadIdx.x; t < D * D; t += 128) s_w1[t] = w1[t];
    if (threadIdx.x < D) { s_b1[threadIdx.x] = b1[threadIdx.x]; s_w2[threadIdx.x] = w2v[threadIdx.x]; }
    if (threadIdx.x == 0) s_b2 = b2s[0];
    __syncthreads();

    int n = blockIdx.x * 128 + threadIdx.x;
    if (n >= NN) return;

    const float4* hp = (const float4*)(g_h + (size_t)n * D);
    float x[D];
#pragma unroll
    for (int q = 0; q < 12; q++) {
        float4 v = hp[q];
        x[4 * q + 0] = v.x; x[4 * q + 1] = v.y; x[4 * q + 2] = v.z; x[4 * q + 3] = v.w;
    }

    float r[D];
    mlp_hidden_reg(x, s_w1, s_b1, r);

    float y = s_b2;
#pragma unroll
    for (int k = 0; k < D; k++) y += r[k] * s_w2[k];

    atomicAdd(&out[gid[n]], y);
}

extern "C" void kernel_launch(void* const* d_in, const int* in_sizes, int n_in,
                              void* d_out, int out_size) {
    const int*   AtomicNum = (const int*)d_in[0];
    const int*   Edge      = (const int*)d_in[1];
    const int*   graph_id  = (const int*)d_in[2];
    const float* emb       = (const float*)d_in[3];
    const float* msg_w1    = (const float*)d_in[4];
    const float* msg_b1    = (const float*)d_in[5];
    const float* msg_w2    = (const float*)d_in[6];
    const float* msg_b2    = (const float*)d_in[7];
    const float* upd_w1    = (const float*)d_in[8];
    const float* upd_b1    = (const float*)d_in[9];
    const float* upd_w2    = (const float*)d_in[10];
    const float* upd_b2    = (const float*)d_in[11];
    const float* ro_w1     = (const float*)d_in[12];
    const float* ro_b1     = (const float*)d_in[13];
    const float* ro_w2     = (const float*)d_in[14];
    const float* ro_b2     = (const float*)d_in[15];
    float* out = (float*)d_out;

    embed_kernel<<<(NN + 127) / 128, 128>>>(AtomicNum, emb);

    const int zero_blocks = (NN * D / 4 + 255) / 256;
    const int edge_blocks = NE / 128;           // exact
    const int node_blocks = (NN + 127) / 128;

    for (int l = 0; l < NL; l++) {
        zero_agg_kernel<<<zero_blocks, 256>>>();
        edge_kernel<<<edge_blocks, 128>>>(Edge,
                                          msg_w1 + (size_t)l * D * D, msg_b1 + (size_t)l * D,
                                          msg_w2 + (size_t)l * D * D, msg_b2 + (size_t)l * D);
        update_kernel<<<node_blocks, 128>>>(upd_w1 + (size_t)l * D * D, upd_b1 + (size_t)l * D,
                                            upd_w2 + (size_t)l * D * D, upd_b2 + (size_t)l * D);
    }

    zero_out_kernel<<<(NG + 255) / 256, 256>>>(out);
    readout_kernel<<<node_blocks, 128>>>(ro_w1, ro_b1, ro_w2, ro_b2, graph_id, out);
}

// round 10
// speedup vs baseline: 1.3922x; 1.0301x over previous
#include <cuda_runtime.h>

#define D   48
#define NN  100000
#define NE  1600000
#define NL  6
#define NG  1000

__device__ __align__(16) float g_h[NN * D];
__device__ __align__(16) float g_agg[NN * D];

typedef unsigned long long u64;

__device__ __forceinline__ u64 pack2(float v) {
    u64 r; asm("mov.b64 %0, {%1, %1};" : "=l"(r) : "f"(v)); return r;
}
__device__ __forceinline__ u64 pkp(float lo, float hi) {
    u64 r; asm("mov.b64 %0, {%1, %2};" : "=l"(r) : "f"(lo), "f"(hi)); return r;
}
__device__ __forceinline__ void unpack2(u64 v, float& lo, float& hi) {
    asm("mov.b64 {%0, %1}, %2;" : "=f"(lo), "=f"(hi) : "l"(v));
}
__device__ __forceinline__ u64 ffma2(u64 a, u64 b, u64 c) {
    u64 d; asm("fma.rn.f32x2 %0, %1, %2, %3;" : "=l"(d) : "l"(a), "l"(b), "l"(c));
    return d;
}

// ---------------------------------------------------------------------------
// Block-GEMM two-layer MLP over 256 items staged in s_x[i*256 + item]
// (i = feature 0..47). 128 threads: thread (a = tid&31, b = tid>>5) computes
// items {a, a+32, ..., a+224} (8 of them) for output slice [b*12, b*12+12).
// Weights/biases are read straight from global (warp-uniform LDG.128,
// L1-resident); x reads are lane-consecutive scalar LDS (conflict-free).
// Accumulation over i ascending in both layers (same order as before).
// On return m[e*12 + j] = output j for item a + 32e.
// ---------------------------------------------------------------------------
__device__ __forceinline__ void mlp2_g8(float* __restrict__ s_x,
                                        const float* __restrict__ gw1,
                                        const float* __restrict__ gb1,
                                        const float* __restrict__ gw2,
                                        const float* __restrict__ gb2,
                                        int a, int b,
                                        float* __restrict__ m) {
    u64 acc[8][6];
    // ---- layer 1 ----
    {
        const float4* bb = (const float4*)(gb1 + b * 12);
        float4 b0 = __ldg(bb), b1 = __ldg(bb + 1), b2 = __ldg(bb + 2);
        u64 c0 = pkp(b0.x, b0.y), c1 = pkp(b0.z, b0.w), c2 = pkp(b1.x, b1.y);
        u64 c3 = pkp(b1.z, b1.w), c4 = pkp(b2.x, b2.y), c5 = pkp(b2.z, b2.w);
#pragma unroll
        for (int e = 0; e < 8; e++) {
            acc[e][0] = c0; acc[e][1] = c1; acc[e][2] = c2;
            acc[e][3] = c3; acc[e][4] = c4; acc[e][5] = c5;
        }
    }
#pragma unroll 2
    for (int i = 0; i < D; i++) {
        const float4* wr = (const float4*)(gw1 + i * D + b * 12);
        float4 wa = __ldg(wr), wb = __ldg(wr + 1), wc = __ldg(wr + 2);
        u64 w0 = pkp(wa.x, wa.y), w1 = pkp(wa.z, wa.w), w2 = pkp(wb.x, wb.y);
        u64 w3 = pkp(wb.z, wb.w), w4 = pkp(wc.x, wc.y), w5 = pkp(wc.z, wc.w);
        const float* xr = s_x + i * 256 + a;
#pragma unroll
        for (int e = 0; e < 8; e++) {
            u64 xx = pack2(xr[32 * e]);
            acc[e][0] = ffma2(xx, w0, acc[e][0]);
            acc[e][1] = ffma2(xx, w1, acc[e][1]);
            acc[e][2] = ffma2(xx, w2, acc[e][2]);
            acc[e][3] = ffma2(xx, w3, acc[e][3]);
            acc[e][4] = ffma2(xx, w4, acc[e][4]);
            acc[e][5] = ffma2(xx, w5, acc[e][5]);
        }
    }

    // layer-1 reads of s_x done -> overwrite with relu'd hidden acts
    __syncthreads();
#pragma unroll
    for (int e = 0; e < 8; e++) {
        float* col = s_x + 32 * e + a;
#pragma unroll
        for (int k = 0; k < 6; k++) {
            float lo, hi; unpack2(acc[e][k], lo, hi);
            col[(b * 12 + 2 * k) * 256]     = fmaxf(lo, 0.f);
            col[(b * 12 + 2 * k + 1) * 256] = fmaxf(hi, 0.f);
        }
    }
    __syncthreads();

    // ---- layer 2 ----
    {
        const float4* bb = (const float4*)(gb2 + b * 12);
        float4 b0 = __ldg(bb), b1 = __ldg(bb + 1), b2 = __ldg(bb + 2);
        u64 c0 = pkp(b0.x, b0.y), c1 = pkp(b0.z, b0.w), c2 = pkp(b1.x, b1.y);
        u64 c3 = pkp(b1.z, b1.w), c4 = pkp(b2.x, b2.y), c5 = pkp(b2.z, b2.w);
#pragma unroll
        for (int e = 0; e < 8; e++) {
            acc[e][0] = c0; acc[e][1] = c1; acc[e][2] = c2;
            acc[e][3] = c3; acc[e][4] = c4; acc[e][5] = c5;
        }
    }
#pragma unroll 2
    for (int i = 0; i < D; i++) {
        const float4* wr = (const float4*)(gw2 + i * D + b * 12);
        float4 wa = __ldg(wr), wb = __ldg(wr + 1), wc = __ldg(wr + 2);
        u64 w0 = pkp(wa.x, wa.y), w1 = pkp(wa.z, wa.w), w2 = pkp(wb.x, wb.y);
        u64 w3 = pkp(wb.z, wb.w), w4 = pkp(wc.x, wc.y), w5 = pkp(wc.z, wc.w);
        const float* xr = s_x + i * 256 + a;
#pragma unroll
        for (int e = 0; e < 8; e++) {
            u64 xx = pack2(xr[32 * e]);
            acc[e][0] = ffma2(xx, w0, acc[e][0]);
            acc[e][1] = ffma2(xx, w1, acc[e][1]);
            acc[e][2] = ffma2(xx, w2, acc[e][2]);
            acc[e][3] = ffma2(xx, w3, acc[e][3]);
            acc[e][4] = ffma2(xx, w4, acc[e][4]);
            acc[e][5] = ffma2(xx, w5, acc[e][5]);
        }
    }

#pragma unroll
    for (int e = 0; e < 8; e++)
#pragma unroll
        for (int k = 0; k < 6; k++)
            unpack2(acc[e][k], m[e * 12 + 2 * k], m[e * 12 + 2 * k + 1]);
}

// register-x single hidden layer (small readout kernel only)
__device__ __forceinline__ void mlp_hidden_reg(const float* x, const float* s_w1,
                                               const float* s_b1, float* r) {
    u64 acc[24];
    const u64* bp = (const u64*)s_b1;
#pragma unroll
    for (int k = 0; k < 24; k++) acc[k] = bp[k];
#pragma unroll 8
    for (int i = 0; i < D; i++) {
        u64 xx = pack2(x[i]);
        const ulonglong2* w = (const ulonglong2*)(s_w1 + i * D);
#pragma unroll
        for (int k = 0; k < 12; k++) {
            ulonglong2 ww = w[k];
            acc[2 * k]     = ffma2(xx, ww.x, acc[2 * k]);
            acc[2 * k + 1] = ffma2(xx, ww.y, acc[2 * k + 1]);
        }
    }
#pragma unroll
    for (int k = 0; k < 24; k++) {
        float lo, hi; unpack2(acc[k], lo, hi);
        r[2 * k]     = fmaxf(lo, 0.f);
        r[2 * k + 1] = fmaxf(hi, 0.f);
    }
}

__global__ void __launch_bounds__(128) embed_kernel(const int* __restrict__ an,
                                                    const float* __restrict__ emb) {
    int n = blockIdx.x * 128 + threadIdx.x;
    if (n >= NN) return;
    const float4* e = (const float4*)(emb + (size_t)an[n] * D);
    float4* hp = (float4*)(g_h + (size_t)n * D);
#pragma unroll
    for (int q = 0; q < 12; q++) hp[q] = e[q];
}

__global__ void __launch_bounds__(256) zero_agg_kernel() {
    int t = blockIdx.x * 256 + threadIdx.x;
    if (t < NN * D / 4) ((float4*)g_agg)[t] = make_float4(0.f, 0.f, 0.f, 0.f);
}

__global__ void __launch_bounds__(256) zero_out_kernel(float* out) {
    int t = blockIdx.x * 256 + threadIdx.x;
    if (t < NG) out[t] = 0.f;
}

// 256 edges per block; NE % 256 == 0 -> no guards
__global__ void __launch_bounds__(128) edge_kernel(const int* __restrict__ edge,
                                                   const float* __restrict__ w1,
                                                   const float* __restrict__ b1,
                                                   const float* __restrict__ w2,
                                                   const float* __restrict__ b2) {
    __shared__ __align__(16) float s_x[D * 256];   // 48 KB: [i][item]

    int tid = threadIdx.x;
    int base = blockIdx.x * 256;

    // fill: thread tid owns items tid and tid+128
#pragma unroll
    for (int h = 0; h < 2; h++) {
        int item = tid + h * 128;
        int e = base + item;
        int src = edge[e];
        int dst = edge[NE + e];
        const float4* hs = (const float4*)(g_h + (size_t)src * D);
        const float4* hd = (const float4*)(g_h + (size_t)dst * D);
        float* col = s_x + item;
#pragma unroll
        for (int q = 0; q < 12; q++) {
            float4 va = hs[q], vb = hd[q];
            col[(4 * q + 0) * 256] = va.x * vb.x;
            col[(4 * q + 1) * 256] = va.y * vb.y;
            col[(4 * q + 2) * 256] = va.z * vb.z;
            col[(4 * q + 3) * 256] = va.w * vb.w;
        }
    }
    __syncthreads();

    int a = tid & 31, b = tid >> 5;
    int dste[8];
#pragma unroll
    for (int e = 0; e < 8; e++) dste[e] = edge[NE + base + 32 * e + a];

    float m[96];
    mlp2_g8(s_x, w1, b1, w2, b2, a, b, m);

#pragma unroll
    for (int e = 0; e < 8; e++) {
        float* aggp = g_agg + (size_t)dste[e] * D + b * 12;
#pragma unroll
        for (int q = 0; q < 3; q++) {
            asm volatile("red.global.add.v4.f32 [%0], {%1, %2, %3, %4};"
                         :: "l"(aggp + 4 * q),
                            "f"(m[e * 12 + 4 * q + 0]), "f"(m[e * 12 + 4 * q + 1]),
                            "f"(m[e * 12 + 4 * q + 2]), "f"(m[e * 12 + 4 * q + 3])
                         : "memory");
        }
    }
}

__global__ void __launch_bounds__(128) update_kernel(const float* __restrict__ w1,
                                                     const float* __restrict__ b1,
                                                     const float* __restrict__ w2,
                                                     const float* __restrict__ b2) {
    __shared__ __align__(16) float s_x[D * 256];

    int tid = threadIdx.x;
    int base = blockIdx.x * 256;

#pragma unroll
    for (int h = 0; h < 2; h++) {
        int item = tid + h * 128;
        int n = base + item;
        float* col = s_x + item;
        if (n < NN) {
            const float4* ap = (const float4*)(g_agg + (size_t)n * D);
#pragma unroll
            for (int q = 0; q < 12; q++) {
                float4 v = ap[q];
                col[(4 * q + 0) * 256] = v.x;
                col[(4 * q + 1) * 256] = v.y;
                col[(4 * q + 2) * 256] = v.z;
                col[(4 * q + 3) * 256] = v.w;
            }
        } else {
#pragma unroll
            for (int q = 0; q < D; q++) col[q * 256] = 0.f;
        }
    }
    __syncthreads();

    int a = tid & 31, b = tid >> 5;
    float u[96];
    mlp2_g8(s_x, w1, b1, w2, b2, a, b, u);

#pragma unroll
    for (int e = 0; e < 8; e++) {
        int n = base + 32 * e + a;
        if (n < NN) {
            float4* hp = (float4*)(g_h + (size_t)n * D + b * 12);
#pragma unroll
            for (int q = 0; q < 3; q++) {
                float4 hv = hp[q];
                hv.x += u[e * 12 + 4 * q + 0];
                hv.y += u[e * 12 + 4 * q + 1];
                hv.z += u[e * 12 + 4 * q + 2];
                hv.w += u[e * 12 + 4 * q + 3];
                hp[q] = hv;
            }
        }
    }
}

__global__ void __launch_bounds__(128) readout_kernel(const float* __restrict__ w1,
                                                      const float* __restrict__ b1,
                                                      const float* __restrict__ w2v,
                                                      const float* __restrict__ b2s,
                                                      const int* __restrict__ gid,
                                                      float* __restrict__ out) {
    __shared__ __align__(16) float s_w1[D * D];
    __shared__ __align__(16) float s_b1[D];
    __shared__ __align__(16) float s_w2[D];
    __shared__ float s_b2;
    for (int t = threadIdx.x; t < D * D; t += 128) s_w1[t] = w1[t];
    if (threadIdx.x < D) { s_b1[threadIdx.x] = b1[threadIdx.x]; s_w2[threadIdx.x] = w2v[threadIdx.x]; }
    if (threadIdx.x == 0) s_b2 = b2s[0];
    __syncthreads();

    int n = blockIdx.x * 128 + threadIdx.x;
    if (n >= NN) return;

    const float4* hp = (const float4*)(g_h + (size_t)n * D);
    float x[D];
#pragma unroll
    for (int q = 0; q < 12; q++) {
        float4 v = hp[q];
        x[4 * q + 0] = v.x; x[4 * q + 1] = v.y; x[4 * q + 2] = v.z; x[4 * q + 3] = v.w;
    }

    float r[D];
    mlp_hidden_reg(x, s_w1, s_b1, r);

    float y = s_b2;
#pragma unroll
    for (int k = 0; k < D; k++) y += r[k] * s_w2[k];

    atomicAdd(&out[gid[n]], y);
}

extern "C" void kernel_launch(void* const* d_in, const int* in_sizes, int n_in,
                              void* d_out, int out_size) {
    const int*   AtomicNum = (const int*)d_in[0];
    const int*   Edge      = (const int*)d_in[1];
    const int*   graph_id  = (const int*)d_in[2];
    const float* emb       = (const float*)d_in[3];
    const float* msg_w1    = (const float*)d_in[4];
    const float* msg_b1    = (const float*)d_in[5];
    const float* msg_w2    = (const float*)d_in[6];
    const float* msg_b2    = (const float*)d_in[7];
    const float* upd_w1    = (const float*)d_in[8];
    const float* upd_b1    = (const float*)d_in[9];
    const float* upd_w2    = (const float*)d_in[10];
    const float* upd_b2    = (const float*)d_in[11];
    const float* ro_w1     = (const float*)d_in[12];
    const float* ro_b1     = (const float*)d_in[13];
    const float* ro_w2     = (const float*)d_in[14];
    const float* ro_b2     = (const float*)d_in[15];
    float* out = (float*)d_out;

    embed_kernel<<<(NN + 127) / 128, 128>>>(AtomicNum, emb);

    const int zero_blocks = (NN * D / 4 + 255) / 256;
    const int edge_blocks = NE / 256;            // exact: 6250
    const int node_blocks = (NN + 255) / 256;    // 391
    const int ro_blocks   = (NN + 127) / 128;

    for (int l = 0; l < NL; l++) {
        zero_agg_kernel<<<zero_blocks, 256>>>();
        edge_kernel<<<edge_blocks, 128>>>(Edge,
                                          msg_w1 + (size_t)l * D * D, msg_b1 + (size_t)l * D,
                                          msg_w2 + (size_t)l * D * D, msg_b2 + (size_t)l * D);
        update_kernel<<<node_blocks, 128>>>(upd_w1 + (size_t)l * D * D, upd_b1 + (size_t)l * D,
                                            upd_w2 + (size_t)l * D * D, upd_b2 + (size_t)l * D);
    }

    zero_out_kernel<<<(NG + 255) / 256, 256>>>(out);
    readout_kernel<<<ro_blocks, 128>>>(ro_w1, ro_b1, ro_w2, ro_b2, graph_id, out);
}